// round 16
// baseline (speedup 1.0000x reference)
#include <cuda_runtime.h>

#define GS      20
#define PARAM   40
#define NN      (GS * PARAM)     // 800
#define NSYS    80               // B*A
#define MST     44               // padded matrix stride

// ---------------------------------------------------------------------------
// One CTA per system, 800 threads.
// P = I(x)S + M(x)Ng,  F = S/2 - I,  G = F^2.
// Bpre = 0.5(I-F)(I+G+G^2): Bpre*S = I - F^6 (bias 1.5e-5, measured).
// C = Bpre*Ng = 0.5(I+G+G^2)(I-F)Ng, built depth-3:
//   P1: G = F*F (warps 0-9) || D = Ng - F*Ng (warps 10-19) || M2 = M*M (rest)
//   P2: R = G*D (warps 0-9) || e = (I(x)G)v (idle 480 threads)
//   P3: C = 0.5(D+R+G*R)    || f = (I(x)G)e, u = v+e+f (in place)
//   P4: b = 0.5(u - (I(x)F)u) = (I(x)Bpre)v ; x0 = b
// Degree-2 solve (== 2 Richardson sweeps, R15-verified rel_err 4.7e-5):
//   T = (I(x)C)b ; T2 = (I(x)C)T ; x = b - (M(x)I)T + (M2(x)I)T2 ; clip.
// ---------------------------------------------------------------------------

#define GM_PLAIN 0   // D = A*Bm
#define GM_DNEG  1   // D = Bm - A*Bm            (D = Ng - F*Ng)
#define GM_CFIN  2   // D = 0.5*(E + Bm + A*Bm)  (C = 0.5(D + R + G*R))

// Warp-cooperative 40x40 GEMM, 10 warps (vt in [0,320)) — R13 tiling, proven.
// Warp w: rows 4w..4w+3.  lane -> rr = lane>>3 (row), cc = lane&7.
// Cols per thread: {2cc,2cc+1}, {2cc+16,2cc+17}, and {2cc+32,2cc+33} if cc<4.
template <int MODE>
__device__ __forceinline__ void gemm40w(float* __restrict__ D,
                                        const float* __restrict__ A,
                                        const float* __restrict__ B,
                                        const float* __restrict__ E,
                                        int vt)
{
    const int lane = vt & 31;
    const int rr   = lane >> 3;           // 0..3
    const int cc   = lane & 7;            // 0..7
    const int r    = 4 * (vt >> 5) + rr;  // 0..39
    const int c0   = 2 * cc;              // 0..15
    const int c1   = c0 + 16;             // 16..31
    const int c2   = c0 + 32;             // 32..39 (cc<4 only)
    const bool has2 = (cc < 4);

    float a00 = 0.f, a01 = 0.f, a10 = 0.f, a11 = 0.f, a20 = 0.f, a21 = 0.f;
    const float4* Arow = (const float4*)(A + r * MST);
    #pragma unroll
    for (int k4 = 0; k4 < 10; ++k4) {
        float4 a4 = Arow[k4];
        #pragma unroll
        for (int j = 0; j < 4; ++j) {
            float av = (j == 0) ? a4.x : (j == 1) ? a4.y : (j == 2) ? a4.z : a4.w;
            const float* Bk = B + (4 * k4 + j) * MST;
            float2 b0 = *(const float2*)(Bk + c0);
            float2 b1 = *(const float2*)(Bk + c1);
            a00 = fmaf(av, b0.x, a00);  a01 = fmaf(av, b0.y, a01);
            a10 = fmaf(av, b1.x, a10);  a11 = fmaf(av, b1.y, a11);
            if (has2) {
                float2 b2 = *(const float2*)(Bk + c2);
                a20 = fmaf(av, b2.x, a20);  a21 = fmaf(av, b2.y, a21);
            }
        }
    }

    #pragma unroll
    for (int s = 0; s < 3; ++s) {
        if (s == 2 && !has2) break;
        int   c  = (s == 0) ? c0 : (s == 1) ? c1 : c2;
        float v0 = (s == 0) ? a00 : (s == 1) ? a10 : a20;
        float v1 = (s == 0) ? a01 : (s == 1) ? a11 : a21;
        float2 o;
        if (MODE == GM_DNEG) {
            o.x = B[r * MST + c]     - v0;
            o.y = B[r * MST + c + 1] - v1;
        } else if (MODE == GM_CFIN) {
            o.x = 0.5f * (E[r * MST + c]     + B[r * MST + c]     + v0);
            o.y = 0.5f * (E[r * MST + c + 1] + B[r * MST + c + 1] + v1);
        } else {
            o.x = v0; o.y = v1;
        }
        *(float2*)(D + r * MST + c) = o;
    }
}

// dot(Mat[p,:], vec[g,:]) with float4 reads
__device__ __forceinline__ float rowdot40(const float* __restrict__ Mrow,
                                          const float* __restrict__ vrow)
{
    const float4* m4 = (const float4*)Mrow;
    const float4* v4 = (const float4*)vrow;
    float acc = 0.f;
    #pragma unroll
    for (int i = 0; i < 10; ++i) {
        float4 m = m4[i], v = v4[i];
        acc = fmaf(m.x, v.x, acc);
        acc = fmaf(m.y, v.y, acc);
        acc = fmaf(m.z, v.z, acc);
        acc = fmaf(m.w, v.w, acc);
    }
    return acc;
}

__global__ __launch_bounds__(NN, 1)
void gliam_fused_kernel(const float* __restrict__ mat,        // (80,20,20)
                        const float* __restrict__ val,        // (80,800)
                        const float* __restrict__ selfintact, // (40,40)
                        const float* __restrict__ neigintact, // (40,40)
                        float* __restrict__ out)              // (80,800)
{
    __shared__ __align__(16) float mF [PARAM * MST];  // F = S/2 - I
    __shared__ __align__(16) float mNg[PARAM * MST];  // Ng
    __shared__ __align__(16) float mG [PARAM * MST];  // G = F^2
    __shared__ __align__(16) float mD [PARAM * MST];  // D = (I-F)Ng
    __shared__ __align__(16) float mR [PARAM * MST];  // R = G*D
    __shared__ __align__(16) float mC [PARAM * MST];  // C = Bpre*Ng
    __shared__ __align__(16) float sx [NN];           // b
    __shared__ __align__(16) float sT [NN];           // T = (I(x)C)b
    __shared__ __align__(16) float sE [NN];           // e, later T2
    __shared__ __align__(16) float sV [NN];           // v, then u (in place)
    __shared__ __align__(16) float sM [GS * GS];      // M
    __shared__ __align__(16) float sM2[GS * GS];      // M^2

    const int sys = blockIdx.x;
    const int t   = threadIdx.x;     // 0..799
    const int g   = t / PARAM;       // 0..19
    const int p   = t % PARAM;       // 0..39

    // ---- stage inputs ----
    {
        int i0 = t, i1 = t + NN;
        int r0 = i0 / PARAM, c0 = i0 % PARAM;
        int r1 = i1 / PARAM, c1 = i1 % PARAM;
        mF [r0 * MST + c0] = 0.5f * selfintact[i0] - (r0 == c0 ? 1.0f : 0.0f);
        mF [r1 * MST + c1] = 0.5f * selfintact[i1] - (r1 == c1 ? 1.0f : 0.0f);
        mNg[r0 * MST + c0] = neigintact[i0];
        mNg[r1 * MST + c1] = neigintact[i1];
        sV[t] = val[sys * NN + t];
        if (t < GS * GS) sM[t] = mat[sys * GS * GS + t];
    }
    __syncthreads();

    // ---- P1: G = F*F || D = Ng - F*Ng || M2 = M*M ----
    if (t < 320) {
        gemm40w<GM_PLAIN>(mG, mF, mF, 0, t);
    } else if (t < 640) {
        gemm40w<GM_DNEG>(mD, mF, mNg, 0, t - 320);
    } else {
        #pragma unroll 1
        for (int idx = t - 640; idx < GS * GS; idx += 160) {
            int i = idx / GS, j = idx % GS;
            float acc = 0.f;
            #pragma unroll
            for (int k = 0; k < GS; ++k)
                acc = fmaf(sM[i * GS + k], sM[k * GS + j], acc);
            sM2[idx] = acc;
        }
    }
    __syncthreads();

    // ---- P2: R = G*D || e = (I(x)G)v ----
    if (t < 320) {
        gemm40w<GM_PLAIN>(mR, mG, mD, 0, t);
    } else {
        int el = t - 320;                 // 0..479
        sE[el] = rowdot40(&mG[(el % PARAM) * MST], &sV[(el / PARAM) * PARAM]);
        if (el < 320) {
            int e2 = el + 480;
            sE[e2] = rowdot40(&mG[(e2 % PARAM) * MST], &sV[(e2 / PARAM) * PARAM]);
        }
    }
    __syncthreads();

    // ---- P3: C = 0.5(D + R + G*R) || f = (I(x)G)e, u = v+e+f (in place) ----
    if (t < 320) {
        gemm40w<GM_CFIN>(mC, mG, mR, mD, t);
    } else {
        int el = t - 320;
        {
            float f = rowdot40(&mG[(el % PARAM) * MST], &sE[(el / PARAM) * PARAM]);
            sV[el] = sV[el] + sE[el] + f;     // each thread touches only its own el
        }
        if (el < 320) {
            int e2 = el + 480;
            float f = rowdot40(&mG[(e2 % PARAM) * MST], &sE[(e2 / PARAM) * PARAM]);
            sV[e2] = sV[e2] + sE[e2] + f;
        }
    }
    __syncthreads();

    // ---- P4: b = 0.5*(u - (I(x)F)u); stage b; load C rows into registers ----
    float b = 0.5f * (sV[t] - rowdot40(&mF[p * MST], &sV[g * PARAM]));
    float4 creg[10];
    #pragma unroll
    for (int i = 0; i < 10; ++i)
        creg[i] = *(const float4*)&mC[p * MST + 4 * i];
    sx[t] = b;                        // sx untouched so far -> no pre-barrier
    __syncthreads();

    // ---- A1: T = (I(x)C) b ----
    {
        const float4* x4r = (const float4*)&sx[g * PARAM];
        float tv = 0.f;
        #pragma unroll
        for (int i = 0; i < 10; ++i) {
            float4 c = creg[i], x4 = x4r[i];
            tv = fmaf(c.x, x4.x, tv);
            tv = fmaf(c.y, x4.y, tv);
            tv = fmaf(c.z, x4.z, tv);
            tv = fmaf(c.w, x4.w, tv);
        }
        sT[t] = tv;
    }
    __syncthreads();

    // ---- A2: T2 = (I(x)C) T  (sE dead -> reuse for T2) ----
    {
        const float4* t4r = (const float4*)&sT[g * PARAM];
        float tv = 0.f;
        #pragma unroll
        for (int i = 0; i < 10; ++i) {
            float4 c = creg[i], x4 = t4r[i];
            tv = fmaf(c.x, x4.x, tv);
            tv = fmaf(c.y, x4.y, tv);
            tv = fmaf(c.z, x4.z, tv);
            tv = fmaf(c.w, x4.w, tv);
        }
        sE[t] = tv;
    }
    __syncthreads();

    // ---- Bf: x = b - (M(x)I)T + (M2(x)I)T2 ; clip ; store ----
    {
        float acc = b;
        const float* Mrow  = &sM [g * GS];
        const float* M2row = &sM2[g * GS];
        #pragma unroll
        for (int g2 = 0; g2 < GS; ++g2) {
            acc = fmaf(-Mrow[g2],  sT[g2 * PARAM + p], acc);
            acc = fmaf( M2row[g2], sE[g2 * PARAM + p], acc);
        }
        acc = fminf(fmaxf(acc, -1.0f), 1.0f);   // advrelu == clip
        out[sys * NN + t] = acc;
    }
}

extern "C" void kernel_launch(void* const* d_in, const int* in_sizes, int n_in,
                              void* d_out, int out_size)
{
    const float* mat        = (const float*)d_in[0];
    const float* val        = (const float*)d_in[1];
    const float* selfintact = (const float*)d_in[2];
    const float* neigintact = (const float*)d_in[3];
    float* out = (float*)d_out;

    gliam_fused_kernel<<<NSYS, NN>>>(mat, val, selfintact, neigintact, out);
}

// round 17
// speedup vs baseline: 1.3375x; 1.3375x over previous
#include <cuda_runtime.h>

#define GS      20
#define PARAM   40
#define NN      (GS * PARAM)     // 800
#define NSYS    80               // B*A
#define MST     44               // padded matrix stride

// ---------------------------------------------------------------------------
// One CTA per system, 800 threads, uniform phases (no warp role-splits).
// P = I(x)S + M(x)Ng,  F = S/2 - I,  G = F^2.
// Bpre = 0.5(I-F)(I+G): Bpre*S = I - F^4  (bias ~6e-4, extrapolated from
// measured F^3=3.8e-3 / F^6=1.5e-5, decay 6.35x per power).
// C = Bpre*Ng = 0.5(I+G)(I-F)Ng = 0.5(D + G*D),  D = Ng - F*Ng.
//   Phase G/D: G = F*F ; D = Ng - F*Ng  (same warps, back-to-back, shared A=F,
//              disjoint outputs -> no barrier between, latency overlaps)
//   Phase C:   C = 0.5(D + G*D)   (epilogue-fused)
//   V1: w = v - (I(x)F)v ;  V2: b = 0.5(w + (I(x)G)w), x0 = b
// Degree-2 solve (== 2 Richardson sweeps, R15-verified truncation 4.7e-5):
//   A1: T=(I(x)C)b ; B1: x1 = b-(M(x)I)T ; A2: T2=(I(x)C)x1 ;
//   B2: x = b-(M(x)I)T2 ; clip ; store.
// ---------------------------------------------------------------------------

#define GM_PLAIN 0   // D = acc
#define GM_DNEG  1   // D = Bm - acc          (D = Ng - F*Ng)
#define GM_CHALF 2   // D = 0.5*(Bm + acc)    (C = 0.5(D + G*D))

// Warp-cooperative 40x40 GEMM, 10 warps (t < 320) — R13 tiling, proven.
// Warp w: rows 4w..4w+3.  lane -> rr = lane>>3 (row), cc = lane&7.
// Cols per thread: {2cc,2cc+1}, {2cc+16,2cc+17}, and {2cc+32,2cc+33} if cc<4.
template <int MODE>
__device__ __forceinline__ void gemm40w(float* __restrict__ D,
                                        const float* __restrict__ A,
                                        const float* __restrict__ B,
                                        int t)
{
    if (t >= 320) return;
    const int lane = t & 31;
    const int rr   = lane >> 3;          // 0..3
    const int cc   = lane & 7;           // 0..7
    const int r    = 4 * (t >> 5) + rr;  // 0..39
    const int c0   = 2 * cc;             // 0..15
    const int c1   = c0 + 16;            // 16..31
    const int c2   = c0 + 32;            // 32..39 (cc<4 only)
    const bool has2 = (cc < 4);

    float a00 = 0.f, a01 = 0.f, a10 = 0.f, a11 = 0.f, a20 = 0.f, a21 = 0.f;
    const float4* Arow = (const float4*)(A + r * MST);
    #pragma unroll
    for (int k4 = 0; k4 < 10; ++k4) {
        float4 a4 = Arow[k4];
        #pragma unroll
        for (int j = 0; j < 4; ++j) {
            float av = (j == 0) ? a4.x : (j == 1) ? a4.y : (j == 2) ? a4.z : a4.w;
            const float* Bk = B + (4 * k4 + j) * MST;
            float2 b0 = *(const float2*)(Bk + c0);
            float2 b1 = *(const float2*)(Bk + c1);
            a00 = fmaf(av, b0.x, a00);  a01 = fmaf(av, b0.y, a01);
            a10 = fmaf(av, b1.x, a10);  a11 = fmaf(av, b1.y, a11);
            if (has2) {
                float2 b2 = *(const float2*)(Bk + c2);
                a20 = fmaf(av, b2.x, a20);  a21 = fmaf(av, b2.y, a21);
            }
        }
    }

    #pragma unroll
    for (int s = 0; s < 3; ++s) {
        if (s == 2 && !has2) break;
        int   c  = (s == 0) ? c0 : (s == 1) ? c1 : c2;
        float v0 = (s == 0) ? a00 : (s == 1) ? a10 : a20;
        float v1 = (s == 0) ? a01 : (s == 1) ? a11 : a21;
        float2 o;
        if (MODE == GM_DNEG) {
            o.x = B[r * MST + c]     - v0;
            o.y = B[r * MST + c + 1] - v1;
        } else if (MODE == GM_CHALF) {
            o.x = 0.5f * (B[r * MST + c]     + v0);
            o.y = 0.5f * (B[r * MST + c + 1] + v1);
        } else {
            o.x = v0; o.y = v1;
        }
        *(float2*)(D + r * MST + c) = o;
    }
}

// dot(Mat[p,:], vec[g,:]) with float4 reads
__device__ __forceinline__ float rowdot40(const float* __restrict__ Mrow,
                                          const float* __restrict__ vrow)
{
    const float4* m4 = (const float4*)Mrow;
    const float4* v4 = (const float4*)vrow;
    float acc = 0.f;
    #pragma unroll
    for (int i = 0; i < 10; ++i) {
        float4 m = m4[i], v = v4[i];
        acc = fmaf(m.x, v.x, acc);
        acc = fmaf(m.y, v.y, acc);
        acc = fmaf(m.z, v.z, acc);
        acc = fmaf(m.w, v.w, acc);
    }
    return acc;
}

__global__ __launch_bounds__(NN, 1)
void gliam_fused_kernel(const float* __restrict__ mat,        // (80,20,20)
                        const float* __restrict__ val,        // (80,800)
                        const float* __restrict__ selfintact, // (40,40)
                        const float* __restrict__ neigintact, // (40,40)
                        float* __restrict__ out)              // (80,800)
{
    __shared__ __align__(16) float mF [PARAM * MST];  // F = S/2 - I
    __shared__ __align__(16) float mNg[PARAM * MST];  // Ng
    __shared__ __align__(16) float mG [PARAM * MST];  // G = F^2
    __shared__ __align__(16) float mD [PARAM * MST];  // D = (I-F)Ng
    __shared__ __align__(16) float mC [PARAM * MST];  // C = 0.5(I+G)D
    __shared__ __align__(16) float sV [NN];           // v
    __shared__ __align__(16) float sW [NN];           // w, later x1
    __shared__ __align__(16) float sx [NN];           // b
    __shared__ __align__(16) float sT [NN];           // T / T2
    __shared__ __align__(16) float sM [GS * GS];      // M

    const int sys = blockIdx.x;
    const int t   = threadIdx.x;     // 0..799
    const int g   = t / PARAM;       // 0..19
    const int p   = t % PARAM;       // 0..39

    // ---- stage inputs ----
    {
        int i0 = t, i1 = t + NN;
        int r0 = i0 / PARAM, c0 = i0 % PARAM;
        int r1 = i1 / PARAM, c1 = i1 % PARAM;
        mF [r0 * MST + c0] = 0.5f * selfintact[i0] - (r0 == c0 ? 1.0f : 0.0f);
        mF [r1 * MST + c1] = 0.5f * selfintact[i1] - (r1 == c1 ? 1.0f : 0.0f);
        mNg[r0 * MST + c0] = neigintact[i0];
        mNg[r1 * MST + c1] = neigintact[i1];
        sV[t] = val[sys * NN + t];
        if (t < GS * GS) sM[t] = mat[sys * GS * GS + t];
    }
    __syncthreads();

    // ---- Phase G/D: G = F*F and D = Ng - F*Ng ----
    // Same warps, back-to-back, NO barrier between: disjoint outputs, both read
    // only F/Ng (stable). Loads of the second overlap FMA drain of the first.
    gemm40w<GM_PLAIN>(mG, mF, mF,  t);
    gemm40w<GM_DNEG >(mD, mF, mNg, t);
    __syncthreads();

    // ---- Phase C: C = 0.5*(D + G*D) ----
    gemm40w<GM_CHALF>(mC, mG, mD, t);
    __syncthreads();

    // ---- V1: w = v - (I(x)F) v ----
    sW[t] = sV[t] - rowdot40(&mF[p * MST], &sV[g * PARAM]);
    __syncthreads();

    // ---- V2: b = 0.5*(w + (I(x)G) w); x0 = b; load C row into registers ----
    float b = 0.5f * (sW[t] + rowdot40(&mG[p * MST], &sW[g * PARAM]));
    float4 creg[10];
    #pragma unroll
    for (int i = 0; i < 10; ++i)
        creg[i] = *(const float4*)&mC[p * MST + 4 * i];
    sx[t] = b;                        // sx untouched so far -> no pre-barrier
    __syncthreads();

    const float* Mrow = &sM[g * GS];

    // ---- A1: T = (I(x)C) b ----
    {
        const float4* x4r = (const float4*)&sx[g * PARAM];
        float tv = 0.f;
        #pragma unroll
        for (int i = 0; i < 10; ++i) {
            float4 c = creg[i], x4 = x4r[i];
            tv = fmaf(c.x, x4.x, tv);
            tv = fmaf(c.y, x4.y, tv);
            tv = fmaf(c.z, x4.z, tv);
            tv = fmaf(c.w, x4.w, tv);
        }
        sT[t] = tv;
    }
    __syncthreads();

    // ---- B1: x1 = b - (M(x)I) T  -> sW (dead after V2) ----
    {
        float acc = b;
        #pragma unroll
        for (int g2 = 0; g2 < GS; ++g2)
            acc = fmaf(-Mrow[g2], sT[g2 * PARAM + p], acc);
        sW[t] = acc;
    }
    __syncthreads();

    // ---- A2: T2 = (I(x)C) x1 -> sT (safe: B1's sT reads fenced above) ----
    {
        const float4* x4r = (const float4*)&sW[g * PARAM];
        float tv = 0.f;
        #pragma unroll
        for (int i = 0; i < 10; ++i) {
            float4 c = creg[i], x4 = x4r[i];
            tv = fmaf(c.x, x4.x, tv);
            tv = fmaf(c.y, x4.y, tv);
            tv = fmaf(c.z, x4.z, tv);
            tv = fmaf(c.w, x4.w, tv);
        }
        sT[t] = tv;
    }
    __syncthreads();

    // ---- B2: x = b - (M(x)I) T2 ; clip ; store ----
    {
        float acc = b;
        #pragma unroll
        for (int g2 = 0; g2 < GS; ++g2)
            acc = fmaf(-Mrow[g2], sT[g2 * PARAM + p], acc);
        acc = fminf(fmaxf(acc, -1.0f), 1.0f);   // advrelu == clip
        out[sys * NN + t] = acc;
    }
}

extern "C" void kernel_launch(void* const* d_in, const int* in_sizes, int n_in,
                              void* d_out, int out_size)
{
    const float* mat        = (const float*)d_in[0];
    const float* val        = (const float*)d_in[1];
    const float* selfintact = (const float*)d_in[2];
    const float* neigintact = (const float*)d_in[3];
    float* out = (float*)d_out;

    gliam_fused_kernel<<<NSYS, NN>>>(mat, val, selfintact, neigintact, out);
}